// round 2
// baseline (speedup 1.0000x reference)
#include <cuda_runtime.h>
#include <cstdint>
#include <cstddef>

#define IN_CH  4096
#define OUT_CH 4096
#define NNZ    838860
#define BATCH  16384

// ---------------- GEMM config ----------------
// CTA tile 128(M) x 256(N) x 32(K); 8 compute warps in 2x4 grid -> 64x64 warp tile;
// + 1 producer warp (288 threads). mma.sync.m16n8k8.tf32.
constexpr int BM = 128, BN = 256, BK = 32;
constexpr int STAGES = 4;
constexpr int ITERS = IN_CH / BK;                  // 128
constexpr int A_BYTES = BM * BK * 4;               // 16384
constexpr int B_BYTES = BN * BK * 4;               // 32768
constexpr int STAGE_BYTES = A_BYTES + B_BYTES;     // 49152
constexpr int SMEM_CTRL = 1024;
constexpr int SMEM_BYTES = SMEM_CTRL + STAGES * STAGE_BYTES;  // 197632

// ---------------- scratch (static __device__ only) ----------------
// A = x, pre-rounded to tf32, pre-permuted into mma fragment order:
//   tile (mblk,kblk) is 4096 contiguous floats:
//   idx = ((s*8 + t)*32 + lane)*4 + w
//   where t=(m%128)/16, s=(k%32)/8, lane=(m%8)*4 + (k%4), w=((m%16)/8) + ((k%8)/4)*2
__device__ float g_xt[(size_t)BATCH * IN_CH];
// B = W (row-major W[n][k] == col-major B(k,n)), fragment order, u-pairs packed for LDS.128:
//   tile (nblk,kblk) is 8192 contiguous floats:
//   idx = ((s*16 + p)*32 + lane)*4 + (u&1)*2 + wk
//   where u=(n%256)/8, p=u/2, s=(k%32)/8, lane=(n%8)*4 + (k%4), wk=(k%8)/4
__device__ float g_wt[(size_t)OUT_CH * IN_CH];
// duplicate-resolution tags (last occurrence wins)
__device__ int   g_tag[(size_t)OUT_CH * IN_CH];

// ---------------- helpers ----------------
__device__ __forceinline__ uint32_t smem_u32(const void* p) {
    uint32_t a;
    asm("{ .reg .u64 t; cvta.to.shared.u64 t, %1; cvt.u32.u64 %0, t; }" : "=r"(a) : "l"(p));
    return a;
}

__device__ __forceinline__ uint32_t f2tf32(float x) {  // round-to-nearest tf32 bit pattern
    uint32_t r;
    asm("cvt.rna.tf32.f32 %0, %1;" : "=r"(r) : "f"(x));
    return r;
}

#define MBARRIER_INIT(addr, cnt) \
    asm volatile("mbarrier.init.shared.b64 [%0], %1;" :: "r"(addr), "r"(cnt) : "memory")

#define MBARRIER_EXPECT_TX(addr, bytes) \
    asm volatile("mbarrier.arrive.expect_tx.shared.b64 _, [%0], %1;" :: "r"(addr), "r"(bytes) : "memory")

#define MBARRIER_ARRIVE(addr) \
    asm volatile("mbarrier.arrive.shared.b64 _, [%0];" :: "r"(addr) : "memory")

#define MBARRIER_WAIT_PARITY(mbar_smem_addr, phase_parity) do {                         \
    uint32_t _mbar = (uint32_t)(mbar_smem_addr);                                        \
    uint32_t _parity = (uint32_t)(phase_parity);                                        \
    uint32_t _done;                                                                     \
    asm volatile("{\n\t.reg .pred p;\n\t"                                               \
        "mbarrier.try_wait.parity.acquire.cta.shared::cta.b64 p, [%1], %2;\n\t"         \
        "selp.b32 %0, 1, 0, p;\n\t}"                                                    \
        : "=r"(_done) : "r"(_mbar), "r"(_parity) : "memory");                           \
    if (!_done) {                                                                       \
        asm volatile("{\n\t.reg .pred P1;\n\t"                                          \
            "WAIT_LOOP_%=:\n\t"                                                         \
            "mbarrier.try_wait.parity.acquire.cta.shared::cta.b64 P1, [%0], %1, 0x989680;\n\t" \
            "@P1 bra.uni WAIT_DONE_%=;\n\t"                                             \
            "bra.uni WAIT_LOOP_%=;\n\t"                                                 \
            "WAIT_DONE_%=:\n\t}"                                                        \
            :: "r"(_mbar), "r"(_parity) : "memory");                                    \
    }                                                                                   \
} while (0)

#define MBARRIER_WAIT_PARITY_RELAXED(mbar_smem_addr, phase_parity) do {                 \
    uint32_t _mbar = (uint32_t)(mbar_smem_addr);                                        \
    uint32_t _parity = (uint32_t)(phase_parity);                                        \
    uint32_t _done;                                                                     \
    asm volatile("{\n\t.reg .pred p;\n\t"                                               \
        "mbarrier.try_wait.parity.relaxed.cta.shared::cta.b64 p, [%1], %2, 0x989680;\n\t" \
        "selp.b32 %0, 1, 0, p;\n\t}"                                                    \
        : "=r"(_done) : "r"(_mbar), "r"(_parity) : "memory");                           \
    if (!_done) {                                                                       \
        asm volatile("{\n\t.reg .pred P1;\n\t"                                          \
            "WAIT_LOOP_%=:\n\t"                                                         \
            "mbarrier.try_wait.parity.relaxed.cta.shared::cta.b64 P1, [%0], %1, 0x989680;\n\t" \
            "@P1 bra.uni WAIT_DONE_%=;\n\t"                                             \
            "bra.uni WAIT_LOOP_%=;\n\t"                                                 \
            "WAIT_DONE_%=:\n\t}"                                                        \
            :: "r"(_mbar), "r"(_parity) : "memory");                                    \
    }                                                                                   \
} while (0)

// descriptor-free 1D bulk TMA: gmem -> shared::cta, completes on mbarrier tx (sm_90 base OK)
__device__ __forceinline__ void bulk_g2s(uint32_t dst, const void* src, uint32_t bytes, uint32_t mbar) {
    asm volatile(
        "cp.async.bulk.shared::cta.global.mbarrier::complete_tx::bytes [%0], [%1], %2, [%3];"
        :: "r"(dst), "l"(src), "r"(bytes), "r"(mbar) : "memory");
}

__device__ __forceinline__ void lds128(uint32_t* r, uint32_t addr) {
    asm volatile("ld.shared.v4.u32 {%0,%1,%2,%3}, [%4];"
                 : "=r"(r[0]), "=r"(r[1]), "=r"(r[2]), "=r"(r[3]) : "r"(addr));
}

__device__ __forceinline__ void mma_tf32(float* c, const uint32_t* a, const uint32_t* b) {
    asm volatile(
        "mma.sync.aligned.m16n8k8.row.col.f32.tf32.tf32.f32 "
        "{%0,%1,%2,%3}, {%4,%5,%6,%7}, {%8,%9}, {%0,%1,%2,%3};"
        : "+f"(c[0]), "+f"(c[1]), "+f"(c[2]), "+f"(c[3])
        : "r"(a[0]), "r"(a[1]), "r"(a[2]), "r"(a[3]), "r"(b[0]), "r"(b[1]));
}

// ---------------- preprocessing kernels ----------------
__global__ void k_init() {
    size_t i = (size_t)blockIdx.x * blockDim.x + threadIdx.x;
    if (i < (size_t)OUT_CH * IN_CH) { g_wt[i] = 0.0f; g_tag[i] = -1; }
}

__global__ void k_tag(const int* __restrict__ rows, const int* __restrict__ cols) {
    int i = blockIdx.x * blockDim.x + threadIdx.x;
    if (i < NNZ) atomicMax(&g_tag[(size_t)rows[i] * IN_CH + cols[i]], i);
}

__global__ void k_scatter(const float* __restrict__ w, const int* __restrict__ rows,
                          const int* __restrict__ cols) {
    int i = blockIdx.x * blockDim.x + threadIdx.x;
    if (i >= NNZ) return;
    int n = rows[i], k = cols[i];
    size_t di = (size_t)n * IN_CH + k;
    if (g_tag[di] != i) return;  // last occurrence wins (sequential scatter semantics)
    int nb = n >> 8;             // n / 256
    int kb = k >> 5;             // k / 32
    int s  = (k >> 3) & 3;       // (k%32)/8
    int u  = (n >> 3) & 31;      // (n%256)/8
    int p  = u >> 1;
    int lane = (n & 7) * 4 + (k & 3);
    int slot = (u & 1) * 2 + ((k >> 2) & 1);
    size_t idx = ((size_t)(nb * 128 + kb)) * 8192 + (size_t)(((s * 16 + p) * 32 + lane) * 4 + slot);
    g_wt[idx] = __uint_as_float(f2tf32(w[i]));
}

__global__ void k_xt(const float* __restrict__ x) {
    size_t i4 = (size_t)blockIdx.x * blockDim.x + threadIdx.x;
    if (i4 >= (size_t)BATCH * IN_CH / 4) return;
    const float4 v = reinterpret_cast<const float4*>(x)[i4];
    int m  = (int)(i4 >> 10);            // IN_CH/4 = 1024 float4 per row
    int k4 = (int)(i4 & 1023) * 4;       // k of first element, k4 % 4 == 0
    int mb = m >> 7;
    int kb = k4 >> 5;
    int t  = (m >> 4) & 7;               // (m%128)/16
    int s  = (k4 >> 3) & 3;              // (k%32)/8
    int w  = ((m >> 3) & 1) + ((k4 >> 2) & 1) * 2;   // same for all 4 elems
    int lane0 = (m & 7) * 4;             // + (k%4) = 0..3
    size_t base = ((size_t)(mb * 128 + kb)) * 4096 + (size_t)(((s * 8 + t) * 32 + lane0) * 4 + w);
    g_xt[base +  0] = __uint_as_float(f2tf32(v.x));
    g_xt[base +  4] = __uint_as_float(f2tf32(v.y));
    g_xt[base +  8] = __uint_as_float(f2tf32(v.z));
    g_xt[base + 12] = __uint_as_float(f2tf32(v.w));
}

// ---------------- GEMM kernel ----------------
__global__ void __launch_bounds__(288, 1)
gemm_kernel(float* __restrict__ out, const float* __restrict__ bias) {
    extern __shared__ char smem[];
    uint32_t sb = smem_u32(smem);
    const int tid  = threadIdx.x;
    const int lane = tid & 31;
    const int wid  = tid >> 5;

    // control block: full(s) at sb+16+16s (count 1, tx), empty(s) at sb+24+16s (count 8)
    if (tid == 0) {
        for (int s = 0; s < STAGES; s++) {
            MBARRIER_INIT(sb + 16 + 16 * s, 1);
            MBARRIER_INIT(sb + 24 + 16 * s, 8);
        }
    }
    __syncthreads();

    const int nblk = blockIdx.x;   // x fastest -> one wave shares W tiles via L2
    const int mblk = blockIdx.y;

    if (wid == 8) {
        // -------- producer warp --------
        if (lane == 0) {
            const float* Ab = g_xt + (size_t)mblk * (size_t)(BM * IN_CH);
            const float* Bb = g_wt + (size_t)nblk * (size_t)(BN * IN_CH);
            for (int i = 0; i < ITERS; i++) {
                int s = i & 3;
                uint32_t fb = sb + 16 + 16 * s, eb = fb + 8;
                MBARRIER_WAIT_PARITY_RELAXED(eb, ((i >> 2) & 1) ^ 1);
                MBARRIER_EXPECT_TX(fb, STAGE_BYTES);
                uint32_t dst = sb + SMEM_CTRL + s * STAGE_BYTES;
                bulk_g2s(dst,           Ab + (size_t)i * (A_BYTES / 4), A_BYTES, fb);
                bulk_g2s(dst + A_BYTES, Bb + (size_t)i * (B_BYTES / 4), B_BYTES, fb);
            }
        }
        return;
    }

    // -------- consumer warps: 2x4 grid, 64x64 warp tile --------
    const int wm = wid >> 2;   // 0..1
    const int wn = wid & 3;    // 0..3

    float c[4][8][4];
    #pragma unroll
    for (int t = 0; t < 4; t++)
        #pragma unroll
        for (int u = 0; u < 8; u++)
            #pragma unroll
            for (int j = 0; j < 4; j++) c[t][u][j] = 0.0f;

    #pragma unroll 1
    for (int i = 0; i < ITERS; i++) {
        int s = i & 3;
        uint32_t fb = sb + 16 + 16 * s;
        MBARRIER_WAIT_PARITY(fb, (i >> 2) & 1);
        uint32_t Ast = sb + SMEM_CTRL + s * STAGE_BYTES;
        uint32_t Bst = Ast + A_BYTES;

        #pragma unroll
        for (int ks = 0; ks < 4; ks++) {
            uint32_t a[4][4], b[4][4];
            #pragma unroll
            for (int t = 0; t < 4; t++)
                lds128(a[t], Ast + (uint32_t)(((ks * 8 + wm * 4 + t) * 32 + lane) * 16));
            #pragma unroll
            for (int pi = 0; pi < 4; pi++)
                lds128(b[pi], Bst + (uint32_t)(((ks * 16 + wn * 4 + pi) * 32 + lane) * 16));
            #pragma unroll
            for (int t = 0; t < 4; t++)
                #pragma unroll
                for (int pi = 0; pi < 4; pi++) {
                    mma_tf32(c[t][2 * pi + 0], a[t], &b[pi][0]);
                    mma_tf32(c[t][2 * pi + 1], a[t], &b[pi][2]);
                }
        }
        __syncwarp();
        if (lane == 0) MBARRIER_ARRIVE(fb + 8);
    }

    // -------- epilogue: fused bias add, float2 stores --------
    const int r0    = lane >> 2;
    const int cpair = (lane & 3) * 2;
    const size_t m0 = (size_t)mblk * BM + (size_t)wm * 64;
    const int    n0 = nblk * BN + wn * 64;

    #pragma unroll
    for (int u = 0; u < 8; u++) {
        const float2 bv = *reinterpret_cast<const float2*>(bias + n0 + u * 8 + cpair);
        #pragma unroll
        for (int t = 0; t < 4; t++) {
            size_t row = m0 + (size_t)(t * 16 + r0);
            float2 v0 = { c[t][u][0] + bv.x, c[t][u][1] + bv.y };
            float2 v1 = { c[t][u][2] + bv.x, c[t][u][3] + bv.y };
            *reinterpret_cast<float2*>(out + row * OUT_CH + n0 + u * 8 + cpair)       = v0;
            *reinterpret_cast<float2*>(out + (row + 8) * OUT_CH + n0 + u * 8 + cpair) = v1;
        }
    }
}

// ---------------- launch ----------------
extern "C" void kernel_launch(void* const* d_in, const int* in_sizes, int n_in,
                              void* d_out, int out_size) {
    const float* x    = (const float*)d_in[0];
    const float* w    = (const float*)d_in[1];
    const float* bias = (const float*)d_in[2];
    const int*   rows = (const int*)d_in[3];
    const int*   cols = (const int*)d_in[4];
    float* out = (float*)d_out;

    k_init<<<(unsigned)(((size_t)OUT_CH * IN_CH + 255) / 256), 256>>>();
    k_tag<<<(NNZ + 255) / 256, 256>>>(rows, cols);
    k_scatter<<<(NNZ + 255) / 256, 256>>>(w, rows, cols);
    k_xt<<<(unsigned)(((size_t)BATCH * IN_CH / 4 + 255) / 256), 256>>>(x);

    cudaFuncSetAttribute(gemm_kernel, cudaFuncAttributeMaxDynamicSharedMemorySize, SMEM_BYTES);
    gemm_kernel<<<dim3(OUT_CH / BN, BATCH / BM), 288, SMEM_BYTES>>>(out, bias);
}

// round 3
// speedup vs baseline: 1.8973x; 1.8973x over previous
#include <cuda_runtime.h>
#include <cuda_fp16.h>
#include <cstdint>
#include <cstddef>

#define IN_CH  4096
#define OUT_CH 4096
#define NNZ    838860
#define BATCH  16384

// ---------------- GEMM config ----------------
// CTA tile 128(M) x 256(N) x 32(K), fp16 operands, fp32 accum.
// 8 compute warps (2x4 -> 64x64 warp tile) + 1 producer warp. mma.sync.m16n8k16.
constexpr int BM = 128, BN = 256, BK = 32;
constexpr int STAGES = 8;
constexpr int ITERS = IN_CH / BK;                  // 128
constexpr int A_BYTES = BM * BK * 2;               // 8192
constexpr int B_BYTES = BN * BK * 2;               // 16384
constexpr int STAGE_BYTES = A_BYTES + B_BYTES;     // 24576
constexpr int SMEM_CTRL = 1024;
constexpr int SMEM_BYTES = SMEM_CTRL + STAGES * STAGE_BYTES;  // 197632

// ---------------- scratch (static __device__ only) ----------------
// A = x as fp16, fragment order. Tile (mblk,kblk) = 4096 halves = 512 uint4 slots.
//   slot = ((ks*8 + tt)*32 + lane), contents {a0,a1,a2,a3} for mma m16n8k16:
//   a0 = x[m0][k0],x[m0][k0+1]; a1 = rows+8; a2 = k+8; a3 = both.
//   m0 = tt*16 + lane/4, k0 = ks*16 + (lane%4)*2 (within tile).
__device__ __half g_xt[(size_t)BATCH * IN_CH];
// B = W as fp16 (W[n][k] == B(k,n) col-major), fragment order.
// Tile (nblk,kblk) = 8192 halves = 1024 slots. slot = ((ks*16 + wn*4 + p)*32 + lane),
// contents {b0(u=2p), b1(u=2p), b0(u=2p+1), b1(u=2p+1)}.
__device__ __half g_wt[(size_t)OUT_CH * IN_CH];
// duplicate-resolution tags (last occurrence wins)
__device__ int    g_tag[(size_t)OUT_CH * IN_CH];

// ---------------- helpers ----------------
__device__ __forceinline__ uint32_t smem_u32(const void* p) {
    uint32_t a;
    asm("{ .reg .u64 t; cvta.to.shared.u64 t, %1; cvt.u32.u64 %0, t; }" : "=r"(a) : "l"(p));
    return a;
}

#define MBARRIER_INIT(addr, cnt) \
    asm volatile("mbarrier.init.shared.b64 [%0], %1;" :: "r"(addr), "r"(cnt) : "memory")

#define MBARRIER_EXPECT_TX(addr, bytes) \
    asm volatile("mbarrier.arrive.expect_tx.shared.b64 _, [%0], %1;" :: "r"(addr), "r"(bytes) : "memory")

#define MBARRIER_ARRIVE(addr) \
    asm volatile("mbarrier.arrive.shared.b64 _, [%0];" :: "r"(addr) : "memory")

#define MBARRIER_WAIT_PARITY(mbar_smem_addr, phase_parity) do {                         \
    uint32_t _mbar = (uint32_t)(mbar_smem_addr);                                        \
    uint32_t _parity = (uint32_t)(phase_parity);                                        \
    uint32_t _done;                                                                     \
    asm volatile("{\n\t.reg .pred p;\n\t"                                               \
        "mbarrier.try_wait.parity.acquire.cta.shared::cta.b64 p, [%1], %2;\n\t"         \
        "selp.b32 %0, 1, 0, p;\n\t}"                                                    \
        : "=r"(_done) : "r"(_mbar), "r"(_parity) : "memory");                           \
    if (!_done) {                                                                       \
        asm volatile("{\n\t.reg .pred P1;\n\t"                                          \
            "WAIT_LOOP_%=:\n\t"                                                         \
            "mbarrier.try_wait.parity.acquire.cta.shared::cta.b64 P1, [%0], %1, 0x989680;\n\t" \
            "@P1 bra.uni WAIT_DONE_%=;\n\t"                                             \
            "bra.uni WAIT_LOOP_%=;\n\t"                                                 \
            "WAIT_DONE_%=:\n\t}"                                                        \
            :: "r"(_mbar), "r"(_parity) : "memory");                                    \
    }                                                                                   \
} while (0)

#define MBARRIER_WAIT_PARITY_RELAXED(mbar_smem_addr, phase_parity) do {                 \
    uint32_t _mbar = (uint32_t)(mbar_smem_addr);                                        \
    uint32_t _parity = (uint32_t)(phase_parity);                                        \
    uint32_t _done;                                                                     \
    asm volatile("{\n\t.reg .pred p;\n\t"                                               \
        "mbarrier.try_wait.parity.relaxed.cta.shared::cta.b64 p, [%1], %2, 0x989680;\n\t" \
        "selp.b32 %0, 1, 0, p;\n\t}"                                                    \
        : "=r"(_done) : "r"(_mbar), "r"(_parity) : "memory");                           \
    if (!_done) {                                                                       \
        asm volatile("{\n\t.reg .pred P1;\n\t"                                          \
            "WAIT_LOOP_%=:\n\t"                                                         \
            "mbarrier.try_wait.parity.relaxed.cta.shared::cta.b64 P1, [%0], %1, 0x989680;\n\t" \
            "@P1 bra.uni WAIT_DONE_%=;\n\t"                                             \
            "bra.uni WAIT_LOOP_%=;\n\t"                                                 \
            "WAIT_DONE_%=:\n\t}"                                                        \
            :: "r"(_mbar), "r"(_parity) : "memory");                                    \
    }                                                                                   \
} while (0)

// descriptor-free 1D bulk TMA: gmem -> shared::cta, completes on mbarrier tx
__device__ __forceinline__ void bulk_g2s(uint32_t dst, const void* src, uint32_t bytes, uint32_t mbar) {
    asm volatile(
        "cp.async.bulk.shared::cta.global.mbarrier::complete_tx::bytes [%0], [%1], %2, [%3];"
        :: "r"(dst), "l"(src), "r"(bytes), "r"(mbar) : "memory");
}

__device__ __forceinline__ void lds128(uint32_t* r, uint32_t addr) {
    asm volatile("ld.shared.v4.u32 {%0,%1,%2,%3}, [%4];"
                 : "=r"(r[0]), "=r"(r[1]), "=r"(r[2]), "=r"(r[3]) : "r"(addr));
}

__device__ __forceinline__ void mma_f16(float* c, const uint32_t* a, const uint32_t* b) {
    asm volatile(
        "mma.sync.aligned.m16n8k16.row.col.f32.f16.f16.f32 "
        "{%0,%1,%2,%3}, {%4,%5,%6,%7}, {%8,%9}, {%0,%1,%2,%3};"
        : "+f"(c[0]), "+f"(c[1]), "+f"(c[2]), "+f"(c[3])
        : "r"(a[0]), "r"(a[1]), "r"(a[2]), "r"(a[3]), "r"(b[0]), "r"(b[1]));
}

// ---------------- preprocessing kernels ----------------
__global__ void k_init() {
    size_t i = (size_t)blockIdx.x * blockDim.x + threadIdx.x;
    if (i < (size_t)OUT_CH * IN_CH) {
        g_tag[i] = -1;
        if (i < (size_t)OUT_CH * IN_CH / 2) reinterpret_cast<uint32_t*>(g_wt)[i] = 0;
    }
}

__global__ void k_tag(const int* __restrict__ rows, const int* __restrict__ cols) {
    int i = blockIdx.x * blockDim.x + threadIdx.x;
    if (i < NNZ) atomicMax(&g_tag[(size_t)rows[i] * IN_CH + cols[i]], i);
}

__global__ void k_scatter(const float* __restrict__ w, const int* __restrict__ rows,
                          const int* __restrict__ cols) {
    int i = blockIdx.x * blockDim.x + threadIdx.x;
    if (i >= NNZ) return;
    int n = rows[i], k = cols[i];
    size_t di = (size_t)n * IN_CH + k;
    if (g_tag[di] != i) return;                // last occurrence wins
    int nb   = n >> 8;                         // n / 256
    int kb   = k >> 5;                         // k / 32
    int ks   = (k >> 4) & 1;                   // k16-chunk within BK
    int kk   = k & 15;
    int bidx = kk >> 3;                        // b0 vs b1
    int h    = kk & 1;                         // half within b32
    int lane = (n & 7) * 4 + ((kk & 7) >> 1);
    int ug   = (n >> 3) & 31;                  // n8-block within 256
    int wn   = ug >> 3, p = (ug >> 1) & 3, pair = ug & 1;
    size_t idx = (size_t)(nb * 128 + kb) * 8192
               + (size_t)((((ks * 16 + wn * 4 + p) * 32 + lane) * 8) + pair * 4 + bidx * 2 + h);
    g_wt[idx] = __float2half_rn(w[i]);
}

__global__ void k_xt(const float* __restrict__ x) {
    uint32_t g = blockIdx.x * blockDim.x + threadIdx.x;   // one uint4 slot per thread
    if (g >= (uint32_t)(BATCH / 128) * (IN_CH / 32) * 512) return;
    int lane = g & 31;
    int row  = (g >> 5) & 15;
    uint32_t tile = g >> 9;
    int kblk = tile & 127;
    int mblk = tile >> 7;
    int ks = row >> 3, tt = row & 7;
    int m0 = mblk * 128 + tt * 16 + (lane >> 2);
    int k0 = kblk * 32 + ks * 16 + (lane & 3) * 2;
    const float* xr = x + (size_t)m0 * IN_CH + k0;
    float2 f0 = *reinterpret_cast<const float2*>(xr);                   // a0
    float2 f1 = *reinterpret_cast<const float2*>(xr + 8 * IN_CH);       // a1
    float2 f2 = *reinterpret_cast<const float2*>(xr + 8);               // a2
    float2 f3 = *reinterpret_cast<const float2*>(xr + 8 * IN_CH + 8);   // a3
    __half2 h0 = __float22half2_rn(f0);
    __half2 h1 = __float22half2_rn(f1);
    __half2 h2 = __float22half2_rn(f2);
    __half2 h3 = __float22half2_rn(f3);
    uint4 v;
    v.x = *reinterpret_cast<uint32_t*>(&h0);
    v.y = *reinterpret_cast<uint32_t*>(&h1);
    v.z = *reinterpret_cast<uint32_t*>(&h2);
    v.w = *reinterpret_cast<uint32_t*>(&h3);
    reinterpret_cast<uint4*>(g_xt)[g] = v;
}

// ---------------- GEMM kernel ----------------
__global__ void __launch_bounds__(288, 1)
gemm_kernel(float* __restrict__ out, const float* __restrict__ bias) {
    extern __shared__ char smem[];
    uint32_t sb = smem_u32(smem);
    const int tid  = threadIdx.x;
    const int lane = tid & 31;
    const int wid  = tid >> 5;

    // ctrl: full(s)=sb+16+16s (count 1 + tx), empty(s)=sb+24+16s (count 8)
    if (tid == 0) {
        for (int s = 0; s < STAGES; s++) {
            MBARRIER_INIT(sb + 16 + 16 * s, 1);
            MBARRIER_INIT(sb + 24 + 16 * s, 8);
        }
    }
    __syncthreads();

    const int nblk = blockIdx.x;   // x fastest -> wave shares W tiles via L2
    const int mblk = blockIdx.y;

    if (wid == 8) {
        if (lane == 0) {
            const char* Ab = reinterpret_cast<const char*>(g_xt) + (size_t)mblk * (BM * IN_CH * 2);
            const char* Bb = reinterpret_cast<const char*>(g_wt) + (size_t)nblk * (BN * IN_CH * 2);
            for (int i = 0; i < ITERS; i++) {
                int s = i & 7;
                uint32_t fb = sb + 16 + 16 * s, eb = fb + 8;
                MBARRIER_WAIT_PARITY_RELAXED(eb, ((i >> 3) & 1) ^ 1);
                MBARRIER_EXPECT_TX(fb, STAGE_BYTES);
                uint32_t dst = sb + SMEM_CTRL + s * STAGE_BYTES;
                bulk_g2s(dst,           Ab + (size_t)i * A_BYTES, A_BYTES, fb);
                bulk_g2s(dst + A_BYTES, Bb + (size_t)i * B_BYTES, B_BYTES, fb);
            }
        }
        return;
    }

    // -------- consumers: 2x4 warp grid, 64x64 warp tile --------
    const int wm = wid >> 2;   // 0..1
    const int wn = wid & 3;    // 0..3

    float c[4][8][4];
    #pragma unroll
    for (int t = 0; t < 4; t++)
        #pragma unroll
        for (int u = 0; u < 8; u++)
            #pragma unroll
            for (int j = 0; j < 4; j++) c[t][u][j] = 0.0f;

    #pragma unroll 1
    for (int i = 0; i < ITERS; i++) {
        int s = i & 7;
        uint32_t fb = sb + 16 + 16 * s;
        MBARRIER_WAIT_PARITY(fb, (i >> 3) & 1);
        uint32_t Ast = sb + SMEM_CTRL + s * STAGE_BYTES;
        uint32_t Bst = Ast + A_BYTES;

        #pragma unroll
        for (int ks = 0; ks < 2; ks++) {
            uint32_t a[4][4], b[4][4];
            #pragma unroll
            for (int t = 0; t < 4; t++)
                lds128(a[t], Ast + (uint32_t)(((ks * 8 + wm * 4 + t) * 32 + lane) * 16));
            #pragma unroll
            for (int p = 0; p < 4; p++)
                lds128(b[p], Bst + (uint32_t)(((ks * 16 + wn * 4 + p) * 32 + lane) * 16));
            #pragma unroll
            for (int t = 0; t < 4; t++)
                #pragma unroll
                for (int p = 0; p < 4; p++) {
                    mma_f16(c[t][2 * p + 0], a[t], &b[p][0]);
                    mma_f16(c[t][2 * p + 1], a[t], &b[p][2]);
                }
        }
        __syncwarp();
        if (lane == 0) MBARRIER_ARRIVE(fb + 8);
    }

    // -------- epilogue: fused bias add, float2 stores --------
    const int r0    = lane >> 2;
    const int cpair = (lane & 3) * 2;
    const size_t m0 = (size_t)mblk * BM + (size_t)wm * 64;
    const int    n0 = nblk * BN + wn * 64;

    #pragma unroll
    for (int u = 0; u < 8; u++) {
        const float2 bv = *reinterpret_cast<const float2*>(bias + n0 + u * 8 + cpair);
        #pragma unroll
        for (int t = 0; t < 4; t++) {
            size_t row = m0 + (size_t)(t * 16 + r0);
            float2 v0 = { c[t][u][0] + bv.x, c[t][u][1] + bv.y };
            float2 v1 = { c[t][u][2] + bv.x, c[t][u][3] + bv.y };
            *reinterpret_cast<float2*>(out + row * OUT_CH + n0 + u * 8 + cpair)       = v0;
            *reinterpret_cast<float2*>(out + (row + 8) * OUT_CH + n0 + u * 8 + cpair) = v1;
        }
    }
}

// ---------------- launch ----------------
extern "C" void kernel_launch(void* const* d_in, const int* in_sizes, int n_in,
                              void* d_out, int out_size) {
    const float* x    = (const float*)d_in[0];
    const float* w    = (const float*)d_in[1];
    const float* bias = (const float*)d_in[2];
    const int*   rows = (const int*)d_in[3];
    const int*   cols = (const int*)d_in[4];
    float* out = (float*)d_out;

    k_init<<<(unsigned)(((size_t)OUT_CH * IN_CH + 255) / 256), 256>>>();
    k_tag<<<(NNZ + 255) / 256, 256>>>(rows, cols);
    k_scatter<<<(NNZ + 255) / 256, 256>>>(w, rows, cols);
    k_xt<<<(unsigned)(((size_t)BATCH * IN_CH / 8 + 255) / 256), 256>>>(x);

    cudaFuncSetAttribute(gemm_kernel, cudaFuncAttributeMaxDynamicSharedMemorySize, SMEM_BYTES);
    gemm_kernel<<<dim3(OUT_CH / BN, BATCH / BM), 288, SMEM_BYTES>>>(out, bias);
}